// round 1
// baseline (speedup 1.0000x reference)
#include <cuda_runtime.h>
#include <cuda_bf16.h>
#include <cstdint>

// Problem constants
#define Bn 256
#define Nn 1152        // 32*6*6 input capsules
#define On 10
#define En 16
#define OE 160         // On*En
#define NTILE 128
#define NTILES 9       // 1152 / 128

// Scratch (device globals: sanctioned scratch mechanism, no runtime allocs)
__device__ float g_uhat[(size_t)Bn * Nn * OE];   // ~189 MB
__device__ float g_blog[Bn * Nn * On];           // routing logits b1
__device__ float g_part[NTILES * Bn * OE];       // per-tile partial s
__device__ float g_v[Bn * OE];                   // v0 / v1

// ---------------------------------------------------------------------------
// squash over E=16 within a warp-half: lanes [l & ~15 .. ] share one o.
// Requires fully-active warps (160 threads = 5 full warps).
__device__ __forceinline__ float squash_val(float sv) {
    float sq = sv * sv;
    sq += __shfl_xor_sync(0xffffffffu, sq, 1);
    sq += __shfl_xor_sync(0xffffffffu, sq, 2);
    sq += __shfl_xor_sync(0xffffffffu, sq, 4);
    sq += __shfl_xor_sync(0xffffffffu, sq, 8);
    return sv * sq / (1.0f + sq) / (sqrtf(sq) + 1e-6f);
}

// ---------------------------------------------------------------------------
// K1: u_hat[b,n,o,e] = sum_d x[b,n,d] * W[n,o,d,e]
// grid (1152 n, 4 b-tiles), 160 threads; thread = (o,e), W row cached in regs.
__global__ void k_uhat(const float* __restrict__ x, const float* __restrict__ W) {
    int n  = blockIdx.x;
    int b0 = blockIdx.y * 64;
    int t  = threadIdx.x;          // 0..159
    int o  = t >> 4, e = t & 15;

    __shared__ float xs[64][8];
    if (t < 128) {
        int b = t >> 1, half = t & 1;
        const float4 v = *(const float4*)(x + ((b0 + b) * Nn + n) * 8 + half * 4);
        *(float4*)(&xs[b][half * 4]) = v;
    }
    float w[8];
#pragma unroll
    for (int d = 0; d < 8; d++)
        w[d] = W[((n * On + o) * 8 + d) * En + e];
    __syncthreads();

    float* outp = g_uhat + (size_t)(b0 * Nn + n) * OE + t;
#pragma unroll 4
    for (int b = 0; b < 64; b++) {
        float u = 0.0f;
#pragma unroll
        for (int d = 0; d < 8; d++) u = fmaf(w[d], xs[b][d], u);
        outp[(size_t)b * (Nn * OE)] = u;
    }
}

// ---------------------------------------------------------------------------
// K2: s0[b,:] = 0.1 * sum_n u_hat[b,n,:]  -> v0 = squash(s0) -> g_v
// grid 256 (b), 320 threads: 8 n-groups x 40 float4 columns.
__global__ void k_s0v0() {
    int b = blockIdx.x, t = threadIdx.x;   // 320
    int grp = t / 40, q = t - grp * 40;

    const float4* up = (const float4*)(g_uhat + (size_t)b * Nn * OE);
    float4 acc = make_float4(0.f, 0.f, 0.f, 0.f);
#pragma unroll 4
    for (int n = grp; n < Nn; n += 8) {
        float4 v = up[n * 40 + q];
        acc.x += v.x; acc.y += v.y; acc.z += v.z; acc.w += v.w;
    }
    __shared__ float4 part[8][40];
    part[grp][q] = acc;
    __syncthreads();

    __shared__ float s[OE];
    if (t < 40) {
        float4 r = part[0][t];
#pragma unroll
        for (int g = 1; g < 8; g++) {
            float4 v = part[g][t];
            r.x += v.x; r.y += v.y; r.z += v.z; r.w += v.w;
        }
        r.x *= 0.1f; r.y *= 0.1f; r.z *= 0.1f; r.w *= 0.1f;
        *(float4*)(&s[t * 4]) = r;
    }
    __syncthreads();
    if (t < OE)
        g_v[b * OE + t] = squash_val(s[t]);
}

// ---------------------------------------------------------------------------
// K3/K5: one routing iteration over an n-tile.
//   b_new[n,o] = (FIRST ? 0 : g_blog) + dot_e(u[n,o,:], v[o,:])
//   c = softmax_o(b_new);  partial_s[o,e] = sum_{n in tile} c[n,o]*u[n,o,e]
// grid (9 tiles, 256 b), 320 threads, ~92KB dynamic smem (u tile resident).
template <bool FIRST>
__global__ void k_route() {
    extern __shared__ float sm[];
    float* u_s = sm;                 // 20480
    float* v_s = u_s + NTILE * OE;   // 160
    float* b1s = v_s + OE;           // 1280
    float* cs  = b1s + NTILE * On;   // 1280
    float* sp  = cs + NTILE * On;    // 320

    int tile = blockIdx.x, b = blockIdx.y;
    int n0 = tile * NTILE;
    int t = threadIdx.x;             // 320

    // Phase A: load u tile (80KB) + v
    const float4* src = (const float4*)(g_uhat + (size_t)(b * Nn + n0) * OE);
    float4* dst = (float4*)u_s;
    for (int i = t; i < NTILE * OE / 4; i += 320) dst[i] = src[i];
    if (t < OE) v_s[t] = g_v[b * OE + t];
    __syncthreads();

    // Phase B: logits b1[n,o]
#pragma unroll
    for (int i = 0; i < 4; i++) {
        int p = t + i * 320;         // 0..1279
        int n = p / On, o = p - n * On;
        const float* ur = u_s + n * OE + o * En;
        const float* vr = v_s + o * En;
        float bb = 0.0f;
#pragma unroll
        for (int k = 0; k < En; k++) bb = fmaf(ur[k], vr[k], bb);
        int gidx = (b * Nn + n0 + n) * On + o;
        if (FIRST) g_blog[gidx] = bb;
        else       bb += g_blog[gidx];
        b1s[p] = bb;
    }
    __syncthreads();

    // Phase C: softmax over o, one thread per n (10 MUFU per 1 n, not per warp)
    if (t < NTILE) {
        const float* br = b1s + t * On;
        float m = br[0];
#pragma unroll
        for (int o = 1; o < On; o++) m = fmaxf(m, br[o]);
        float ex[On]; float ssum = 0.0f;
#pragma unroll
        for (int o = 0; o < On; o++) { ex[o] = __expf(br[o] - m); ssum += ex[o]; }
        float inv = 1.0f / ssum;
        float* cr = cs + t * On;
#pragma unroll
        for (int o = 0; o < On; o++) cr[o] = ex[o] * inv;
    }
    __syncthreads();

    // Phase D: weighted partial sum over the tile (2 thread-groups x 160)
    {
        int g = t / OE, oe = t - g * OE;
        int o = oe >> 4;
        float acc = 0.0f;
        int nb = g * 64;
#pragma unroll 8
        for (int n = nb; n < nb + 64; n++)
            acc = fmaf(cs[n * On + o], u_s[n * OE + oe], acc);
        sp[g * OE + oe] = acc;
    }
    __syncthreads();
    if (t < OE)
        g_part[(tile * Bn + b) * OE + t] = sp[t] + sp[OE + t];
}

// ---------------------------------------------------------------------------
// K4/K6: reduce 9 tile partials -> s; v = squash(s); write g_v or d_out.
__global__ void k_finish(float* out) {
    int b = blockIdx.x, t = threadIdx.x;  // 160
    float acc = 0.0f;
#pragma unroll
    for (int tl = 0; tl < NTILES; tl++)
        acc += g_part[(tl * Bn + b) * OE + t];
    float v = squash_val(acc);
    if (out) out[b * OE + t] = v;
    else     g_v[b * OE + t] = v;
}

// ---------------------------------------------------------------------------
extern "C" void kernel_launch(void* const* d_in, const int* in_sizes, int n_in,
                              void* d_out, int out_size) {
    const float* x = (const float*)d_in[0];
    const float* W = (const float*)d_in[1];
    if (n_in >= 2 && in_sizes[0] == 1474560) {  // defensive: swapped order
        x = (const float*)d_in[1];
        W = (const float*)d_in[0];
    }
    float* out = (float*)d_out;

    const int smem_route = (NTILE * OE + OE + NTILE * On + NTILE * On + 2 * OE) * 4;
    cudaFuncSetAttribute(k_route<true>,  cudaFuncAttributeMaxDynamicSharedMemorySize, smem_route);
    cudaFuncSetAttribute(k_route<false>, cudaFuncAttributeMaxDynamicSharedMemorySize, smem_route);

    k_uhat<<<dim3(Nn, 4), 160>>>(x, W);                       // u_hat -> HBM
    k_s0v0<<<Bn, 320>>>();                                    // s0 -> v0
    k_route<true><<<dim3(NTILES, Bn), 320, smem_route>>>();   // iter 1: b1, s1 partials
    k_finish<<<Bn, OE>>>(nullptr);                            // v1
    k_route<false><<<dim3(NTILES, Bn), 320, smem_route>>>();  // iter 2: s2 partials
    k_finish<<<Bn, OE>>>(out);                                // v -> d_out
}

// round 4
// speedup vs baseline: 2.6233x; 2.6233x over previous
#include <cuda_runtime.h>
#include <cuda_fp16.h>
#include <cstdint>

// Problem constants
#define Bn 256
#define Nn 1152        // 32*6*6 input capsules
#define On 10
#define En 16
#define OE 160         // On*En
#define Dn 8
#define NC 32          // n per k_uhat block
#define K1T (Nn / NC)  // 36 n-tiles in k_uhat
#define BC 32          // b per k_uhat block
#define NTILE 128
#define NTILES 9       // 1152 / 128

// Scratch (device globals)
__device__ __half g_uhat[(size_t)Bn * Nn * OE];  // ~94 MB fp16
__device__ float  g_part[K1T * Bn * OE];         // per-tile partial s (5.9 MB)
__device__ float  g_v[Bn * OE];                  // v0, then v0+v1 (the logit vector)

// ---------------------------------------------------------------------------
// squash over E=16 within a warp-half. Requires fully-active warps.
__device__ __forceinline__ float squash_val(float sv) {
    float sq = sv * sv;
    sq += __shfl_xor_sync(0xffffffffu, sq, 1);
    sq += __shfl_xor_sync(0xffffffffu, sq, 2);
    sq += __shfl_xor_sync(0xffffffffu, sq, 4);
    sq += __shfl_xor_sync(0xffffffffu, sq, 8);
    return sv * sq / (1.0f + sq) / (sqrtf(sq) + 1e-6f);
}

// ---------------------------------------------------------------------------
// K1: u_hat[b,n,o,e] = sum_d x[b,n,d] * W[n,o,d,e]  (fp16 out)
//     + fused partial s0: g_part[tile][b][oe] = sum_{n in tile} u
// grid (36 n-tiles, 8 b-tiles), 320 threads = 4 b-groups x 80 (o,e-pair).
__global__ void k_uhat(const float* __restrict__ x, const float* __restrict__ W) {
    int nb = blockIdx.x * NC;
    int b0 = blockIdx.y * BC;
    int t  = threadIdx.x;              // 0..319

    __shared__ float xs[BC][NC][Dn];   // 32 KB, [b][n][d]
    for (int i = t; i < BC * NC * Dn / 4; i += 320) {  // 2048 float4
        int b = i >> 6, q = i & 63;
        float4 v = *(const float4*)(x + ((size_t)(b0 + b) * Nn + nb) * Dn + q * 4);
        int n = q >> 1, h = q & 1;
        *(float4*)(&xs[b][n][h * 4]) = v;
    }
    __syncthreads();

    int g = t / 80, p = t - g * 80;    // g: b-group (8 b each), p: (o, e-pair)
    int o = p >> 3, e2 = p & 7;        // e = 2*e2, 2*e2+1  -> oe = 2*p

    float2 acc[8];
#pragma unroll
    for (int b = 0; b < 8; b++) acc[b] = make_float2(0.f, 0.f);

    __half2* uh = (__half2*)g_uhat;
    for (int n = 0; n < NC; n++) {
        float2 w[8];
        const float2* wp = (const float2*)(W + (size_t)((nb + n) * On + o) * (Dn * En)) + e2;
#pragma unroll
        for (int d = 0; d < 8; d++) w[d] = wp[d * 8];  // stride En floats = 8 float2
#pragma unroll
        for (int b = 0; b < 8; b++) {
            int bb = g * 8 + b;
            float u0 = 0.f, u1 = 0.f;
#pragma unroll
            for (int d = 0; d < 8; d++) {
                float xv = xs[bb][n][d];
                u0 = fmaf(w[d].x, xv, u0);
                u1 = fmaf(w[d].y, xv, u1);
            }
            acc[b].x += u0; acc[b].y += u1;
            uh[((size_t)(b0 + bb) * Nn + nb + n) * 80 + p] = __floats2half2_rn(u0, u1);
        }
    }
#pragma unroll
    for (int b = 0; b < 8; b++) {
        int bb = g * 8 + b;
        *(float2*)(g_part + ((size_t)blockIdx.x * Bn + b0 + bb) * OE + 2 * p) = acc[b];
    }
}

// ---------------------------------------------------------------------------
// Route iteration: logits = u . g_v ; softmax over o ; weighted partial sums.
// g_v holds v0 (iter 1) or v0+v1 (iter 2) — logits are additive from b=0.
// grid (9 tiles, 256 b), 320 threads, ~54 KB dynamic smem.
__global__ void k_route() {
    extern __shared__ char sm[];
    __half2* u_s = (__half2*)sm;                    // 40960 B (128 x 80 half2)
    float* v_s = (float*)(sm + NTILE * OE * 2);     // 640
    float* b1s = v_s + OE;                          // 5120
    float* cs  = b1s + NTILE * On;                  // 5120
    float* sp  = cs + NTILE * On;                   // 2560 (4 x 160)

    int tile = blockIdx.x, b = blockIdx.y, t = threadIdx.x;
    int n0 = tile * NTILE;

    // Phase A: load fp16 u tile (40 KB) + v
    const float4* src = (const float4*)(g_uhat + ((size_t)b * Nn + n0) * OE);
    float4* dst = (float4*)u_s;
#pragma unroll
    for (int i = 0; i < 8; i++) dst[t + i * 320] = src[t + i * 320];
    if (t < OE) v_s[t] = g_v[b * OE + t];
    __syncthreads();

    // Phase B: logits b1[n,o] = dot_e(u, v)
#pragma unroll
    for (int i = 0; i < 4; i++) {
        int pp = t + i * 320;          // 0..1279
        int n = pp / On, o = pp - n * On;
        const __half2* ur = u_s + n * 80 + o * 8;
        const float* vr = v_s + o * En;
        float bb = 0.f;
#pragma unroll
        for (int k = 0; k < 8; k++) {
            float2 uf = __half22float2(ur[k]);
            bb = fmaf(uf.x, vr[2 * k], bb);
            bb = fmaf(uf.y, vr[2 * k + 1], bb);
        }
        b1s[pp] = bb;
    }
    __syncthreads();

    // Phase C: softmax over o, one thread per n
    if (t < NTILE) {
        const float* br = b1s + t * On;
        float m = br[0];
#pragma unroll
        for (int o = 1; o < On; o++) m = fmaxf(m, br[o]);
        float ex[On]; float ssum = 0.f;
#pragma unroll
        for (int o = 0; o < On; o++) { ex[o] = __expf(br[o] - m); ssum += ex[o]; }
        float inv = 1.0f / ssum;
        float* cr = cs + t * On;
#pragma unroll
        for (int o = 0; o < On; o++) cr[o] = ex[o] * inv;
    }
    __syncthreads();

    // Phase D: weighted partial sums (4 n-groups x 80 oe-pairs)
    {
        int g = t / 80, p = t - g * 80;
        int o = p >> 3;
        float2 a = make_float2(0.f, 0.f);
        int nb2 = g * 32;
#pragma unroll 8
        for (int n = nb2; n < nb2 + 32; n++) {
            float c = cs[n * On + o];
            float2 uf = __half22float2(u_s[n * 80 + p]);
            a.x = fmaf(c, uf.x, a.x);
            a.y = fmaf(c, uf.y, a.y);
        }
        *(float2*)(sp + g * OE + 2 * p) = a;
    }
    __syncthreads();
    if (t < OE)
        g_part[((size_t)tile * Bn + b) * OE + t] =
            ((sp[t] + sp[OE + t]) + sp[2 * OE + t]) + sp[3 * OE + t];
}

// ---------------------------------------------------------------------------
// Reduce partials -> s -> squash.
// mode 0: s0 = 0.1*sum(36 tiles), v0 -> g_v
// mode 1: v1 = squash(sum 9 tiles); g_v += v1 (vsum for iter-2 logits)
// mode 2: v2 -> out
__global__ void k_finish(float* out, int mode) {
    int b = blockIdx.x, t = threadIdx.x;  // 160
    float acc = 0.f;
    if (mode == 0) {
#pragma unroll 4
        for (int tl = 0; tl < K1T; tl++) acc += g_part[((size_t)tl * Bn + b) * OE + t];
        g_v[b * OE + t] = squash_val(acc * 0.1f);
    } else {
#pragma unroll
        for (int tl = 0; tl < NTILES; tl++) acc += g_part[((size_t)tl * Bn + b) * OE + t];
        float v = squash_val(acc);
        if (mode == 1) g_v[b * OE + t] += v;
        else           out[b * OE + t] = v;
    }
}

// ---------------------------------------------------------------------------
extern "C" void kernel_launch(void* const* d_in, const int* in_sizes, int n_in,
                              void* d_out, int out_size) {
    const float* x = (const float*)d_in[0];
    const float* W = (const float*)d_in[1];
    if (n_in >= 2 && in_sizes[0] == 1474560) {  // defensive: swapped order
        x = (const float*)d_in[1];
        W = (const float*)d_in[0];
    }
    float* out = (float*)d_out;

    const int smem_route = NTILE * OE * 2 + (OE + 2 * NTILE * On + 4 * OE) * 4;
    cudaFuncSetAttribute(k_route, cudaFuncAttributeMaxDynamicSharedMemorySize, smem_route);

    k_uhat<<<dim3(K1T, Bn / BC), 320>>>(x, W);            // u_hat fp16 + s0 partials
    k_finish<<<Bn, OE>>>(nullptr, 0);                     // v0
    k_route<<<dim3(NTILES, Bn), 320, smem_route>>>();     // iter 1 partials
    k_finish<<<Bn, OE>>>(nullptr, 1);                     // v1, g_v = v0+v1
    k_route<<<dim3(NTILES, Bn), 320, smem_route>>>();     // iter 2 partials
    k_finish<<<Bn, OE>>>(out, 2);                         // v2 -> d_out
}